// round 10
// baseline (speedup 1.0000x reference)
#include <cuda_runtime.h>
#include <cstdint>

typedef unsigned long long ull;

#define BT   192
#define SEQ  207
#define CC   128
#define RED  64
#define DIN  128
#define DS   16
#define XD   36
#define NROWS (BT*SEQ)     // 39744
#define NR2   (2*NROWS)    // 79488

// ---------------- scratch (no allocation allowed) ----------------
__device__ float g_h0[NROWS*RED];       // 10.2 MB
__device__ float g_u [2*NROWS*DIN];     // 40.7 MB  (pre-conv u, un-reversed)
__device__ float g_uc[2*NROWS*DIN];     // 40.7 MB  (post conv+silu, scan order)
__device__ float g_z [2*NROWS*DIN];     // 40.7 MB  (z pre-gate, un-reversed)
__device__ float g_xd[2*NROWS*XD];      // 11.4 MB  (xdbl, scan order)
__device__ float g_y [2*NROWS*DIN];     // 40.7 MB  (gated y, un-reversed order)
__device__ float g_s [NROWS*RED];       // 10.2 MB  (fw+bw outproj sum)

// ---------------- f32x2 packed-FMA helpers ----------------
__device__ __forceinline__ ull f2pk(float lo, float hi){ ull r; asm("mov.b64 %0,{%1,%2};" : "=l"(r) : "f"(lo), "f"(hi)); return r; }
__device__ __forceinline__ ull f2bc(float v){ return f2pk(v, v); }
__device__ __forceinline__ ull f2fma(ull a, ull b, ull c){ ull d; asm("fma.rn.f32x2 %0,%1,%2,%3;" : "=l"(d) : "l"(a), "l"(b), "l"(c)); return d; }
__device__ __forceinline__ float2 f2up(ull v){ float2 r; asm("mov.b64 {%0,%1},%2;" : "=f"(r.x), "=f"(r.y) : "l"(v)); return r; }

struct ScanW { const float *dtw, *dtb, *Alog, *D; };

// =================================================================
// K1: h0 = LN_256(concat(x,qk)) @ in_w + in_b        64 rows / CTA
// =================================================================
#define K1_SMEM ((256*64 + 64*257)*4)   // 131328 B
__global__ void __launch_bounds__(256) k1_pre(
    const float* __restrict__ x, const float* __restrict__ qk,
    const float* __restrict__ lnw, const float* __restrict__ lnb,
    const float* __restrict__ W,   const float* __restrict__ Wb)
{
    extern __shared__ float sm[];
    float* s_w = sm;            // [256][64]
    float* s_a = sm + 256*64;   // [64][257]
    int tid = threadIdx.x;

    for (int i = tid; i < 4096; i += 256) ((float4*)s_w)[i] = ((const float4*)W)[i];

    int base = blockIdx.x * 64;
    int warp = tid >> 5, lane = tid & 31;
#pragma unroll
    for (int j = 0; j < 8; j++) {
        int rl = warp*8 + j;
        size_t row = (size_t)(base + rl);
        const float* xr = x  + row*CC;
        const float* qr = qk + row*CC;
        float v[8], sum = 0.f, sq = 0.f;
#pragma unroll
        for (int k = 0; k < 8; k++) {
            int i = lane + 32*k;
            float val = (i < CC) ? xr[i] : qr[i - CC];
            v[k] = val; sum += val; sq += val*val;
        }
#pragma unroll
        for (int off = 16; off; off >>= 1) {
            sum += __shfl_xor_sync(0xffffffffu, sum, off);
            sq  += __shfl_xor_sync(0xffffffffu, sq,  off);
        }
        float mean = sum * (1.f/256.f);
        float var  = sq  * (1.f/256.f) - mean*mean;
        float rstd = rsqrtf(var + 1e-5f);
#pragma unroll
        for (int k = 0; k < 8; k++) {
            int i = lane + 32*k;
            s_a[rl*257 + i] = (v[k]-mean)*rstd*lnw[i] + lnb[i];
        }
    }
    __syncthreads();

    // GEMM 256->64: thread = 4 rows x 4 cols (2 f32x2)
    int colg = tid & 15, rowg = tid >> 4;
    ull b0 = ((const ull*)Wb)[colg*2], b1 = ((const ull*)Wb)[colg*2+1];
    ull acc[4][2];
#pragma unroll
    for (int ri = 0; ri < 4; ri++) { acc[ri][0] = b0; acc[ri][1] = b1; }
    const ull* w8 = (const ull*)s_w;
#pragma unroll 2
    for (int k = 0; k < 256; k++) {
        ull w0 = w8[k*32 + colg*2], w1 = w8[k*32 + colg*2 + 1];
#pragma unroll
        for (int ri = 0; ri < 4; ri++) {
            ull a2 = f2bc(s_a[(rowg*4+ri)*257 + k]);
            acc[ri][0] = f2fma(a2, w0, acc[ri][0]);
            acc[ri][1] = f2fma(a2, w1, acc[ri][1]);
        }
    }
#pragma unroll
    for (int ri = 0; ri < 4; ri++) {
        ull* dst = (ull*)(g_h0 + (size_t)(base + rowg*4 + ri)*64 + colg*4);
        dst[0] = acc[ri][0]; dst[1] = acc[ri][1];
    }
}

// =================================================================
// K2: xz = h0 @ inproj  -> g_u (cols 0..127), g_z (cols 128..255)
//     grid (621, dir).  64 rows/CTA, thread = 8 rows x 8 cols.
// =================================================================
#define K2_SMEM ((64*256 + 64*64)*4)    // 81920 B
__global__ void __launch_bounds__(256) k2_inproj(
    const float* __restrict__ fw_ip, const float* __restrict__ bw_ip)
{
    extern __shared__ float sm[];
    float* s_w = sm;            // [64][256]
    float* s_a = sm + 64*256;   // [64][64]
    int tid = threadIdx.x;
    int dir = blockIdx.y;
    const float* W = dir ? bw_ip : fw_ip;

    for (int i = tid; i < 4096; i += 256) ((float4*)s_w)[i] = ((const float4*)W)[i];
    int base = blockIdx.x * 64;
    for (int i = tid; i < 1024; i += 256)
        ((float4*)s_a)[i] = ((const float4*)(g_h0 + (size_t)base*64))[i];
    __syncthreads();

    int colg = tid & 31, rowg = tid >> 5;   // 8 cols (4 ull), 8 rows
    ull acc[8][4];
#pragma unroll
    for (int ri = 0; ri < 8; ri++)
#pragma unroll
        for (int c = 0; c < 4; c++) acc[ri][c] = 0ull;
    const ull* w8 = (const ull*)s_w;
#pragma unroll 2
    for (int k = 0; k < 64; k++) {
        ull w0 = w8[k*128 + colg*4 + 0];
        ull w1 = w8[k*128 + colg*4 + 1];
        ull w2 = w8[k*128 + colg*4 + 2];
        ull w3 = w8[k*128 + colg*4 + 3];
#pragma unroll
        for (int ri = 0; ri < 8; ri++) {
            ull a2 = f2bc(s_a[(rowg*8+ri)*64 + k]);
            acc[ri][0] = f2fma(a2, w0, acc[ri][0]);
            acc[ri][1] = f2fma(a2, w1, acc[ri][1]);
            acc[ri][2] = f2fma(a2, w2, acc[ri][2]);
            acc[ri][3] = f2fma(a2, w3, acc[ri][3]);
        }
    }
    float* dstb = (colg < 16) ? g_u : g_z;
    int col0 = (colg < 16) ? colg*8 : colg*8 - 128;
#pragma unroll
    for (int ri = 0; ri < 8; ri++) {
        ull* dst = (ull*)(dstb + ((size_t)dir*NROWS + base + rowg*8 + ri)*128 + col0);
        dst[0] = acc[ri][0]; dst[1] = acc[ri][1];
        dst[2] = acc[ri][2]; dst[3] = acc[ri][3];
    }
}

// =================================================================
// K3: depthwise causal conv(K=4)+silu, per (dir,b,d); scan-order out
// =================================================================
__global__ void __launch_bounds__(256) k3_conv(
    const float* __restrict__ fcw, const float* __restrict__ fcb,
    const float* __restrict__ bcw, const float* __restrict__ bcb)
{
    int idx = blockIdx.x*256 + threadIdx.x;   // < 2*192*128 = 49152
    int d  = idx & 127;
    int rb = idx >> 7;            // 0..383
    int b   = rb % BT;
    int dir = rb / BT;
    const float* cw = dir ? bcw : fcw;
    const float* cb = dir ? bcb : fcb;
    float w0 = cw[d*4+0], w1 = cw[d*4+1], w2 = cw[d*4+2], w3 = cw[d*4+3];
    float bb = cb[d];
    const float* src = g_u  + ((size_t)dir*NROWS + (size_t)b*SEQ)*128 + d;
    float*       dst = g_uc + ((size_t)dir*NROWS + (size_t)b*SEQ)*128 + d;
    float p3 = 0.f, p2 = 0.f, p1 = 0.f;
    if (dir == 0) {
#pragma unroll 4
        for (int t = 0; t < SEQ; t++) {
            float cur = src[t*128];
            float v = fmaf(w0,p3, fmaf(w1,p2, fmaf(w2,p1, fmaf(w3,cur, bb))));
            dst[t*128] = v / (1.f + __expf(-v));
            p3 = p2; p2 = p1; p1 = cur;
        }
    } else {
#pragma unroll 4
        for (int t = 0; t < SEQ; t++) {
            float cur = src[(SEQ-1-t)*128];
            float v = fmaf(w0,p3, fmaf(w1,p2, fmaf(w2,p1, fmaf(w3,cur, bb))));
            dst[t*128] = v / (1.f + __expf(-v));
            p3 = p2; p2 = p1; p1 = cur;
        }
    }
}

// =================================================================
// K4: xd = uc @ xproj   (row/thread, 18 f32x2 accs, 256 rows/CTA)
// =================================================================
#define K4_PITCH 132
#define K4_SMEM ((256*K4_PITCH + 2*128*XD)*4)   // 135168 + 36864 = 172032 B
__global__ void __launch_bounds__(256) k4_xproj(
    const float* __restrict__ fxp, const float* __restrict__ bxp)
{
    extern __shared__ float sm[];
    float* s_a  = sm;                    // [256][132]
    float* s_xp = sm + 256*K4_PITCH;     // [2][128][36]
    int tid = threadIdx.x;
    int base = blockIdx.x * 256;

    for (int i = tid; i < 8192; i += 256) {
        int r = i >> 5, c = i & 31;
        int grow = base + r;
        if (grow < NR2)
            ((float4*)(s_a + r*K4_PITCH))[c] = ((const float4*)(g_uc + (size_t)grow*128))[c];
    }
    for (int i = tid; i < 2304; i += 256)
        ((float4*)s_xp)[i] = (i < 1152) ? ((const float4*)fxp)[i]
                                        : ((const float4*)bxp)[i - 1152];
    __syncthreads();

    int row = base + tid;
    if (row >= NR2) return;
    int dir = (row >= NROWS);
    const ull* w8 = (const ull*)(s_xp + dir*(128*XD));
    const float* ar = s_a + tid*K4_PITCH;
    ull acc[18];
#pragma unroll
    for (int j = 0; j < 18; j++) acc[j] = 0ull;
#pragma unroll 2
    for (int k = 0; k < 128; k++) {
        ull a2 = f2bc(ar[k]);
#pragma unroll
        for (int j = 0; j < 18; j++) acc[j] = f2fma(a2, w8[k*18 + j], acc[j]);
    }
    ull* dst = (ull*)(g_xd + (size_t)row*XD);
#pragma unroll
    for (int j = 0; j < 18; j++) dst[j] = acc[j];
}

// =================================================================
// K5: selective scan + gate.  CTA per (b,dir); 2 threads/channel.
// =================================================================
#define K5_SMEM ((SEQ*DIN + SEQ*XD)*4)   // 135792 B
__global__ void __launch_bounds__(256, 1) k5_scan(ScanW fw, ScanW bw)
{
    extern __shared__ float sm[];
    float* s_u  = sm;             // [207][128] uc, later y
    float* s_xd = sm + SEQ*DIN;   // [207][36]
    int b = blockIdx.x, dir = blockIdx.y;
    int tid = threadIdx.x;
    size_t rowbase = (size_t)dir*NROWS + (size_t)b*SEQ;

    for (int i = tid; i < SEQ*DIN/4; i += 256)
        ((float4*)s_u)[i] = ((const float4*)(g_uc + rowbase*128))[i];
    for (int i = tid; i < SEQ*XD/4; i += 256)
        ((float4*)s_xd)[i] = ((const float4*)(g_xd + rowbase*XD))[i];
    __syncthreads();

    const ScanW p = dir ? bw : fw;
    {
        int d = tid >> 1, nh = tid & 1;
        float dtw0 = p.dtw[0*DIN+d], dtw1 = p.dtw[1*DIN+d];
        float dtw2 = p.dtw[2*DIN+d], dtw3 = p.dtw[3*DIN+d];
        float dtbv = p.dtb[d];
        float Dv   = p.D[d];
        float negA[8];
#pragma unroll
        for (int n = 0; n < 8; n++) negA[n] = -expf(p.Alog[d*DS + nh*8 + n]);
        float hs[8];
#pragma unroll
        for (int n = 0; n < 8; n++) hs[n] = 0.f;

        for (int t = 0; t < SEQ; t++) {
            const float* xr = s_xd + t*XD;
            float dtraw = fmaf(xr[0],dtw0, fmaf(xr[1],dtw1,
                          fmaf(xr[2],dtw2, fmaf(xr[3],dtw3, dtbv))));
            float dt = (dtraw > 20.f) ? dtraw : __logf(1.f + __expf(dtraw));
            float ut = s_u[t*DIN + d];
            float dtu = dt * ut;
            float part = 0.f;
#pragma unroll
            for (int n = 0; n < 8; n++) {
                float a = __expf(dt * negA[n]);
                hs[n] = fmaf(hs[n], a, dtu * xr[4 + nh*8 + n]);
                part  = fmaf(hs[n], xr[20 + nh*8 + n], part);
            }
            part += __shfl_xor_sync(0xffffffffu, part, 1);
            if (nh == 0) s_u[t*DIN + d] = fmaf(ut, Dv, part);
        }
    }
    __syncthreads();

    // gate with silu(z) and write back in ORIGINAL (un-reversed) order
    const float* zsrc = g_z + rowbase*128;
    float*       ydst = g_y + rowbase*128;
    for (int i = tid; i < SEQ*DIN; i += 256) {
        int t = i >> 7, d = i & 127;
        int to = dir ? (SEQ-1-t) : t;
        float y = s_u[t*DIN + d];
        float z = zsrc[to*128 + d];
        ydst[to*128 + d] = y * (z / (1.f + __expf(-z)));
    }
}

// =================================================================
// K6: s = y_fw @ fw_outproj + y_bw @ bw_outproj   (64 rows/CTA)
// =================================================================
#define K6_YP 132
#define K6_SMEM ((2*128*64 + 2*64*K6_YP)*4)   // 65536 + 67584 = 133120 B
__global__ void __launch_bounds__(256) k6_outproj(
    const float* __restrict__ fop, const float* __restrict__ bop)
{
    extern __shared__ float sm[];
    float* s_op = sm;                // [2][128][64]
    float* s_y  = sm + 2*128*64;     // [2][64][132]
    int tid = threadIdx.x;
    int base = blockIdx.x * 64;

    for (int i = tid; i < 4096; i += 256)
        ((float4*)s_op)[i] = (i < 2048) ? ((const float4*)fop)[i]
                                        : ((const float4*)bop)[i - 2048];
    for (int i = tid; i < 4096; i += 256) {
        int dir = i >> 11, r = (i >> 5) & 63, c = i & 31;
        ((float4*)(s_y + dir*64*K6_YP + r*K6_YP))[c] =
            ((const float4*)(g_y + ((size_t)dir*NROWS + base + r)*128))[c];
    }
    __syncthreads();

    int colg = tid & 15, rowg = tid >> 4;    // 4 cols (2 ull), 4 rows
    ull acc[4][2];
#pragma unroll
    for (int ri = 0; ri < 4; ri++) { acc[ri][0] = 0ull; acc[ri][1] = 0ull; }
#pragma unroll
    for (int dir = 0; dir < 2; dir++) {
        const ull*  w8 = (const ull*)(s_op + dir*128*64);
        const float* ya = s_y + dir*64*K6_YP;
#pragma unroll 2
        for (int k = 0; k < 128; k++) {
            ull w0 = w8[k*32 + colg*2], w1 = w8[k*32 + colg*2 + 1];
#pragma unroll
            for (int ri = 0; ri < 4; ri++) {
                ull a2 = f2bc(ya[(rowg*4+ri)*K6_YP + k]);
                acc[ri][0] = f2fma(a2, w0, acc[ri][0]);
                acc[ri][1] = f2fma(a2, w1, acc[ri][1]);
            }
        }
    }
#pragma unroll
    for (int ri = 0; ri < 4; ri++) {
        ull* dst = (ull*)(g_s + (size_t)(base + rowg*4 + ri)*64 + colg*4);
        dst[0] = acc[ri][0]; dst[1] = acc[ri][1];
    }
}

// =================================================================
// K7: LN64(s)@ov_w+ov_b + x  ->  LN128 @ o_w + o_b   (64 rows/CTA)
// =================================================================
#define K7_TP 132
#define K7_SMEM ((64*128 + 128*128 + 64*65 + 2*64*K7_TP)*4)  // 182528 B
__global__ void __launch_bounds__(256) k7_post(
    const float* __restrict__ ovlnw, const float* __restrict__ ovlnb,
    const float* __restrict__ ovw,   const float* __restrict__ ovb,
    const float* __restrict__ olnw,  const float* __restrict__ olnb,
    const float* __restrict__ ow,    const float* __restrict__ ob,
    const float* __restrict__ xin,   float* __restrict__ out)
{
    extern __shared__ float sm[];
    float* s_vw = sm;                       // [64][128]
    float* s_ow = sm + 8192;                // [128][128]
    float* s_v  = sm + 24576;               // [64][65]
    float* s_t  = sm + 24576 + 64*65;       // [64][132]
    float* s_l  = s_t + 64*K7_TP;           // [64][132]
    int tid = threadIdx.x;
    int base = blockIdx.x * 64;
    int warp = tid >> 5, lane = tid & 31;

    for (int i = tid; i < 2048; i += 256) ((float4*)s_vw)[i] = ((const float4*)ovw)[i];
    for (int i = tid; i < 4096; i += 256) ((float4*)s_ow)[i] = ((const float4*)ow)[i];

    // LN64 of g_s rows
#pragma unroll
    for (int j = 0; j < 8; j++) {
        int rl = warp*8 + j;
        size_t row = (size_t)(base + rl);
        float v0 = g_s[row*64 + lane];
        float v1 = g_s[row*64 + 32 + lane];
        float sum = v0 + v1, sq = v0*v0 + v1*v1;
#pragma unroll
        for (int off = 16; off; off >>= 1) {
            sum += __shfl_xor_sync(0xffffffffu, sum, off);
            sq  += __shfl_xor_sync(0xffffffffu, sq,  off);
        }
        float mean = sum * (1.f/64.f);
        float var  = sq  * (1.f/64.f) - mean*mean;
        float rstd = rsqrtf(var + 1e-5f);
        s_v[rl*65 + lane]      = (v0-mean)*rstd*ovlnw[lane]    + ovlnb[lane];
        s_v[rl*65 + 32 + lane] = (v1-mean)*rstd*ovlnw[32+lane] + ovlnb[32+lane];
    }
    __syncthreads();

    int colg = tid & 31, rowg = tid >> 5;   // 4 cols (2 ull), 8 rows

    // GEMM1 64->128, + bias + residual, into s_t
    {
        ull b0 = ((const ull*)ovb)[colg*2], b1 = ((const ull*)ovb)[colg*2+1];
        ull acc[8][2];
#pragma unroll
        for (int ri = 0; ri < 8; ri++) { acc[ri][0] = b0; acc[ri][1] = b1; }
        const ull* w8 = (const ull*)s_vw;
#pragma unroll 2
        for (int k = 0; k < 64; k++) {
            ull w0 = w8[k*64 + colg*2], w1 = w8[k*64 + colg*2 + 1];
#pragma unroll
            for (int ri = 0; ri < 8; ri++) {
                ull a2 = f2bc(s_v[(rowg*8+ri)*65 + k]);
                acc[ri][0] = f2fma(a2, w0, acc[ri][0]);
                acc[ri][1] = f2fma(a2, w1, acc[ri][1]);
            }
        }
#pragma unroll
        for (int ri = 0; ri < 8; ri++) {
            int rl = rowg*8 + ri;
            float4 xv = ((const float4*)(xin + (size_t)(base + rl)*128))[colg];
            float2 a0 = f2up(acc[ri][0]), a1 = f2up(acc[ri][1]);
            float4 o;
            o.x = a0.x + xv.x; o.y = a0.y + xv.y;
            o.z = a1.x + xv.z; o.w = a1.y + xv.w;
            ((float4*)(s_t + rl*K7_TP))[colg] = o;
        }
    }
    __syncthreads();

    // LN128
#pragma unroll
    for (int j = 0; j < 8; j++) {
        int rl = warp*8 + j;
        float v[4]; float sum = 0.f, sq = 0.f;
#pragma unroll
        for (int k = 0; k < 4; k++) {
            v[k] = s_t[rl*K7_TP + lane + 32*k];
            sum += v[k]; sq += v[k]*v[k];
        }
#pragma unroll
        for (int off = 16; off; off >>= 1) {
            sum += __shfl_xor_sync(0xffffffffu, sum, off);
            sq  += __shfl_xor_sync(0xffffffffu, sq,  off);
        }
        float mean = sum * (1.f/128.f);
        float var  = sq  * (1.f/128.f) - mean*mean;
        float rstd = rsqrtf(var + 1e-5f);
#pragma unroll
        for (int k = 0; k < 4; k++) {
            int i = lane + 32*k;
            s_l[rl*K7_TP + i] = (v[k]-mean)*rstd*olnw[i] + olnb[i];
        }
    }
    __syncthreads();

    // GEMM2 128->128
    {
        ull b0 = ((const ull*)ob)[colg*2], b1 = ((const ull*)ob)[colg*2+1];
        ull acc[8][2];
#pragma unroll
        for (int ri = 0; ri < 8; ri++) { acc[ri][0] = b0; acc[ri][1] = b1; }
        const ull* w8 = (const ull*)s_ow;
#pragma unroll 2
        for (int k = 0; k < 128; k++) {
            ull w0 = w8[k*64 + colg*2], w1 = w8[k*64 + colg*2 + 1];
#pragma unroll
            for (int ri = 0; ri < 8; ri++) {
                ull a2 = f2bc(s_l[(rowg*8+ri)*K7_TP + k]);
                acc[ri][0] = f2fma(a2, w0, acc[ri][0]);
                acc[ri][1] = f2fma(a2, w1, acc[ri][1]);
            }
        }
#pragma unroll
        for (int ri = 0; ri < 8; ri++) {
            ull* dst = (ull*)(out + (size_t)(base + rowg*8 + ri)*128 + colg*4);
            dst[0] = acc[ri][0]; dst[1] = acc[ri][1];
        }
    }
}

// =================================================================
extern "C" void kernel_launch(void* const* d_in, const int* in_sizes, int n_in,
                              void* d_out, int out_size)
{
    (void)n_in; (void)out_size;

    // Disambiguate serialization order (dict vs signature) via slot-6 size:
    // dict order -> slot 6 = ov_ln_w (64); signature order -> fw_inproj (16384).
    bool sig_order = (in_sizes[6] > 1024);
    int i_ov, i_fw, i_bw;
    if (sig_order) { i_fw = 6;  i_bw = 15; i_ov = 24; }
    else           { i_ov = 6;  i_fw = 14; i_bw = 23; }

    const float* x     = (const float*)d_in[0];
    const float* qk    = (const float*)d_in[1];
    const float* inlnw = (const float*)d_in[2];
    const float* inlnb = (const float*)d_in[3];
    const float* inw   = (const float*)d_in[4];
    const float* inb   = (const float*)d_in[5];

    // mamba groups: inproj,convw,convb,xproj,dtw,dtb,Alog,D,outproj
    const float* fw_ip = (const float*)d_in[i_fw+0];
    const float* fw_cw = (const float*)d_in[i_fw+1];
    const float* fw_cb = (const float*)d_in[i_fw+2];
    const float* fw_xp = (const float*)d_in[i_fw+3];
    ScanW fw { (const float*)d_in[i_fw+4], (const float*)d_in[i_fw+5],
               (const float*)d_in[i_fw+6], (const float*)d_in[i_fw+7] };
    const float* fw_op = (const float*)d_in[i_fw+8];

    const float* bw_ip = (const float*)d_in[i_bw+0];
    const float* bw_cw = (const float*)d_in[i_bw+1];
    const float* bw_cb = (const float*)d_in[i_bw+2];
    const float* bw_xp = (const float*)d_in[i_bw+3];
    ScanW bw { (const float*)d_in[i_bw+4], (const float*)d_in[i_bw+5],
               (const float*)d_in[i_bw+6], (const float*)d_in[i_bw+7] };
    const float* bw_op = (const float*)d_in[i_bw+8];

    const float* ovlnw = (const float*)d_in[i_ov+0];
    const float* ovlnb = (const float*)d_in[i_ov+1];
    const float* ovw   = (const float*)d_in[i_ov+2];
    const float* ovb   = (const float*)d_in[i_ov+3];
    const float* olnw  = (const float*)d_in[i_ov+4];
    const float* olnb  = (const float*)d_in[i_ov+5];
    const float* ow    = (const float*)d_in[i_ov+6];
    const float* ob    = (const float*)d_in[i_ov+7];

    cudaFuncSetAttribute(k1_pre,     cudaFuncAttributeMaxDynamicSharedMemorySize, K1_SMEM);
    cudaFuncSetAttribute(k2_inproj,  cudaFuncAttributeMaxDynamicSharedMemorySize, K2_SMEM);
    cudaFuncSetAttribute(k4_xproj,   cudaFuncAttributeMaxDynamicSharedMemorySize, K4_SMEM);
    cudaFuncSetAttribute(k5_scan,    cudaFuncAttributeMaxDynamicSharedMemorySize, K5_SMEM);
    cudaFuncSetAttribute(k6_outproj, cudaFuncAttributeMaxDynamicSharedMemorySize, K6_SMEM);
    cudaFuncSetAttribute(k7_post,    cudaFuncAttributeMaxDynamicSharedMemorySize, K7_SMEM);

    k1_pre    <<<NROWS/64, 256, K1_SMEM>>>(x, qk, inlnw, inlnb, inw, inb);
    k2_inproj <<<dim3(NROWS/64, 2), 256, K2_SMEM>>>(fw_ip, bw_ip);
    k3_conv   <<<(2*BT*DIN)/256, 256>>>(fw_cw, fw_cb, bw_cw, bw_cb);
    k4_xproj  <<<(NR2 + 255)/256, 256, K4_SMEM>>>(fw_xp, bw_xp);
    k5_scan   <<<dim3(BT, 2), 256, K5_SMEM>>>(fw, bw);
    k6_outproj<<<NROWS/64, 256, K6_SMEM>>>(fw_op, bw_op);
    k7_post   <<<NROWS/64, 256, K7_SMEM>>>(ovlnw, ovlnb, ovw, ovb,
                                           olnw, olnb, ow, ob,
                                           x, (float*)d_out);
}

// round 13
// speedup vs baseline: 1.0616x; 1.0616x over previous
#include <cuda_runtime.h>
#include <cstdint>

typedef unsigned long long ull;

#define BT   192
#define SEQ  207
#define CC   128
#define RED  64
#define DIN  128
#define DS   16
#define XD   36
#define NROWS (BT*SEQ)     // 39744
#define SEG  69            // 3 segments of 69 = 207

// ---------------- scratch (no allocation allowed) ----------------
__device__ float g_h0[NROWS*RED];       // 10.2 MB  (pre-proj, original order)
__device__ float g_uc[2*NROWS*DIN];     // 40.7 MB  (post conv+silu, scan order)
__device__ float g_z [2*NROWS*DIN];     // 40.7 MB  (z pre-gate, original order)
__device__ float g_xd[2*NROWS*XD];      // 11.4 MB  (xdbl, scan order)
__device__ float g_s0[NROWS*RED];       // 10.2 MB  (fw outproj partial)
__device__ float g_s1[NROWS*RED];       // 10.2 MB  (bw outproj partial)

// ---------------- f32x2 packed-FMA helpers ----------------
__device__ __forceinline__ ull f2pk(float lo, float hi){ ull r; asm("mov.b64 %0,{%1,%2};" : "=l"(r) : "f"(lo), "f"(hi)); return r; }
__device__ __forceinline__ ull f2bc(float v){ return f2pk(v, v); }
__device__ __forceinline__ ull f2fma(ull a, ull b, ull c){ ull d; asm("fma.rn.f32x2 %0,%1,%2,%3;" : "=l"(d) : "l"(a), "l"(b), "l"(c)); return d; }
__device__ __forceinline__ float2 f2up(ull v){ float2 r; asm("mov.b64 {%0,%1},%2;" : "=f"(r.x), "=f"(r.y) : "l"(v)); return r; }

struct ScanW { const float *dtw, *dtb, *Alog, *D; };

// =================================================================
// K1: h0 = LN_256(concat(x,qk)) @ in_w + in_b        64 rows / CTA
// =================================================================
#define K1_SMEM ((256*64 + 64*257)*4)   // 131328 B
__global__ void __launch_bounds__(256) k1_pre(
    const float* __restrict__ x, const float* __restrict__ qk,
    const float* __restrict__ lnw, const float* __restrict__ lnb,
    const float* __restrict__ W,   const float* __restrict__ Wb)
{
    extern __shared__ float sm[];
    float* s_w = sm;            // [256][64]
    float* s_a = sm + 256*64;   // [64][257]
    int tid = threadIdx.x;

    for (int i = tid; i < 4096; i += 256) ((float4*)s_w)[i] = ((const float4*)W)[i];

    int base = blockIdx.x * 64;
    int warp = tid >> 5, lane = tid & 31;
#pragma unroll
    for (int j = 0; j < 8; j++) {
        int rl = warp*8 + j;
        size_t row = (size_t)(base + rl);
        const float* xr = x  + row*CC;
        const float* qr = qk + row*CC;
        float v[8], sum = 0.f, sq = 0.f;
#pragma unroll
        for (int k = 0; k < 8; k++) {
            int i = lane + 32*k;
            float val = (i < CC) ? xr[i] : qr[i - CC];
            v[k] = val; sum += val; sq += val*val;
        }
#pragma unroll
        for (int off = 16; off; off >>= 1) {
            sum += __shfl_xor_sync(0xffffffffu, sum, off);
            sq  += __shfl_xor_sync(0xffffffffu, sq,  off);
        }
        float mean = sum * (1.f/256.f);
        float var  = sq  * (1.f/256.f) - mean*mean;
        float rstd = rsqrtf(var + 1e-5f);
#pragma unroll
        for (int k = 0; k < 8; k++) {
            int i = lane + 32*k;
            s_a[rl*257 + i] = (v[k]-mean)*rstd*lnw[i] + lnb[i];
        }
    }
    __syncthreads();

    int colg = tid & 15, rowg = tid >> 4;
    ull b0 = ((const ull*)Wb)[colg*2], b1 = ((const ull*)Wb)[colg*2+1];
    ull acc[4][2];
#pragma unroll
    for (int ri = 0; ri < 4; ri++) { acc[ri][0] = b0; acc[ri][1] = b1; }
    const ull* w8 = (const ull*)s_w;
#pragma unroll 2
    for (int k = 0; k < 256; k++) {
        ull w0 = w8[k*32 + colg*2], w1 = w8[k*32 + colg*2 + 1];
#pragma unroll
        for (int ri = 0; ri < 4; ri++) {
            ull a2 = f2bc(s_a[(rowg*4+ri)*257 + k]);
            acc[ri][0] = f2fma(a2, w0, acc[ri][0]);
            acc[ri][1] = f2fma(a2, w1, acc[ri][1]);
        }
    }
#pragma unroll
    for (int ri = 0; ri < 4; ri++) {
        ull* dst = (ull*)(g_h0 + (size_t)(base + rowg*4 + ri)*64 + colg*4);
        dst[0] = acc[ri][0]; dst[1] = acc[ri][1];
    }
}

// =================================================================
// KB: fused inproj + causal conv + silu + xproj + z.
//     CTA = (seg, b, dir).  72 SMEM rows = 3 halo + 69 live.
// =================================================================
#define KB_UP   132                    // padded pitch for s_u
#define KB_H0o  0
#define KB_Uo   (72*64)                // 4608
#define KB_Wo   (KB_Uo + 72*KB_UP)     // 4608 + 9504 = 14112
#define KB_XPo  (KB_Wo + 64*256)       // 30496
#define KB_TOT  (KB_XPo + 128*XD)      // 35104 floats
#define KB_SMEM (KB_TOT*4)             // 140416 B

__global__ void __launch_bounds__(256) kB_fused(
    const float* __restrict__ fip, const float* __restrict__ bip,
    const float* __restrict__ fcw, const float* __restrict__ fcb,
    const float* __restrict__ bcw, const float* __restrict__ bcb,
    const float* __restrict__ fxp, const float* __restrict__ bxp)
{
    extern __shared__ float sm[];
    float* s_h0 = sm + KB_H0o;   // [72][64]
    float* s_u  = sm + KB_Uo;    // [72][132]
    float* s_w  = sm + KB_Wo;    // [64][256]
    float* s_xp = sm + KB_XPo;   // [128][36]

    int seg = blockIdx.x;        // 0..2
    int b   = blockIdx.y;
    int dir = blockIdx.z;
    int s0  = seg * SEG;
    int tid = threadIdx.x;

    const float* ip = dir ? bip : fip;
    const float* xp = dir ? bxp : fxp;

    for (int i = tid; i < 4096; i += 256) ((float4*)s_w)[i]  = ((const float4*)ip)[i];
    for (int i = tid; i < 1152; i += 256) ((float4*)s_xp)[i] = ((const float4*)xp)[i];

    // h0 rows li 0..71  (ts = s0 + li - 3; zero below 0)
    for (int i = tid; i < 72*16; i += 256) {
        int li = i >> 4, c = i & 15;
        int ts = s0 + li - 3;
        float4 v = {0.f,0.f,0.f,0.f};
        if (ts >= 0) {
            int to = dir ? (206 - ts) : ts;
            v = ((const float4*)(g_h0 + ((size_t)b*SEQ + to)*64))[c];
        }
        ((float4*)(s_h0 + li*64))[c] = v;
    }
    __syncthreads();

    // ---- GEMM: [72][64] @ W[64][256] ; cols<128 -> s_u, cols>=128 -> g_z ----
    {
        int colg = tid & 63;     // 4 float cols [colg*4, +4)
        int rowg = tid >> 6;     // rows [rowg*18, +18), in 3 chunks of 6
        const ull* w8 = (const ull*)s_w;
#pragma unroll
        for (int chunk = 0; chunk < 3; chunk++) {
            int r0 = rowg*18 + chunk*6;
            ull acc[6][2];
#pragma unroll
            for (int ri = 0; ri < 6; ri++) { acc[ri][0] = 0ull; acc[ri][1] = 0ull; }
#pragma unroll 2
            for (int k = 0; k < 64; k++) {
                ull w0 = w8[k*128 + colg*2], w1 = w8[k*128 + colg*2 + 1];
#pragma unroll
                for (int ri = 0; ri < 6; ri++) {
                    ull a2 = f2bc(s_h0[(r0+ri)*64 + k]);
                    acc[ri][0] = f2fma(a2, w0, acc[ri][0]);
                    acc[ri][1] = f2fma(a2, w1, acc[ri][1]);
                }
            }
            if (colg < 32) {
#pragma unroll
                for (int ri = 0; ri < 6; ri++) {
                    ull* dst = (ull*)(s_u + (r0+ri)*KB_UP + colg*4);
                    dst[0] = acc[ri][0]; dst[1] = acc[ri][1];
                }
            } else {
                int zc = colg*4 - 128;
#pragma unroll
                for (int ri = 0; ri < 6; ri++) {
                    int li = r0 + ri;
                    if (li >= 3) {                      // live rows only
                        int ts = s0 + li - 3;
                        int to = dir ? (206 - ts) : ts;
                        ull* dst = (ull*)(g_z + ((size_t)dir*NROWS + (size_t)b*SEQ + to)*128 + zc);
                        dst[0] = acc[ri][0]; dst[1] = acc[ri][1];
                    }
                }
            }
        }
    }
    __syncthreads();

    // ---- conv(K=4) + silu, in place over s_u rows [3,72) ----
    {
        int d = tid & 127, half = tid >> 7;
        const float* cw = dir ? bcw : fcw;
        const float* cb = dir ? bcb : fcb;
        float w0 = cw[d*4+0], w1 = cw[d*4+1], w2 = cw[d*4+2], w3 = cw[d*4+3];
        float bb = cb[d];
        int l0 = half ? 38 : 3;
        int l1 = half ? 72 : 38;
        float p3 = s_u[(l0-3)*KB_UP + d];
        float p2 = s_u[(l0-2)*KB_UP + d];
        float p1 = s_u[(l0-1)*KB_UP + d];
        __syncthreads();                 // pre-reads before in-place writes
        float* ucg = g_uc + ((size_t)dir*NROWS + (size_t)b*SEQ)*128 + d;
        for (int li = l0; li < l1; li++) {
            float cur = s_u[li*KB_UP + d];
            float v = fmaf(w0,p3, fmaf(w1,p2, fmaf(w2,p1, fmaf(w3,cur, bb))));
            v = v / (1.f + __expf(-v));
            s_u[li*KB_UP + d] = v;
            ucg[(s0 + li - 3)*128] = v;
            p3 = p2; p2 = p1; p1 = cur;
        }
    }
    __syncthreads();

    // ---- xproj: uc rows [3,72) @ xp[128][36] -> g_xd (scan order) ----
    if (tid < 3*SEG) {
        int r = tid / 3, j = tid % 3;    // row r of 69; j covers 6 ull cols
        int li = r + 3;
        int ts = s0 + r;
        const ull* w8 = (const ull*)s_xp;   // [128][18] ull
        const float* ur = s_u + li*KB_UP;
        ull acc[6];
#pragma unroll
        for (int c = 0; c < 6; c++) acc[c] = 0ull;
#pragma unroll 2
        for (int k = 0; k < 128; k++) {
            ull a2 = f2bc(ur[k]);
#pragma unroll
            for (int c = 0; c < 6; c++)
                acc[c] = f2fma(a2, w8[k*18 + j*6 + c], acc[c]);
        }
        ull* dst = (ull*)(g_xd + ((size_t)dir*NROWS + (size_t)b*SEQ + ts)*XD + j*12);
#pragma unroll
        for (int c = 0; c < 6; c++) dst[c] = acc[c];
    }
}

// =================================================================
// K5: scan + gate + outproj.  CTA per (b,dir); 2 threads/channel.
// =================================================================
#define K5_SMEM ((SEQ*DIN + SEQ*XD + 128*64)*4)   // 168560 B
__global__ void __launch_bounds__(256, 1) k5_scan(
    ScanW fw, ScanW bw,
    const float* __restrict__ fop, const float* __restrict__ bop)
{
    extern __shared__ float sm[];
    float* s_u  = sm;                      // [207][128] uc, later gated y
    float* s_xd = sm + SEQ*DIN;            // [207][36]
    float* s_op = sm + SEQ*DIN + SEQ*XD;   // [128][64]
    int b = blockIdx.x, dir = blockIdx.y;
    int tid = threadIdx.x;
    size_t rowbase = (size_t)dir*NROWS + (size_t)b*SEQ;

    for (int i = tid; i < SEQ*DIN/4; i += 256)
        ((float4*)s_u)[i] = ((const float4*)(g_uc + rowbase*128))[i];
    for (int i = tid; i < SEQ*XD/4; i += 256)
        ((float4*)s_xd)[i] = ((const float4*)(g_xd + rowbase*XD))[i];
    {
        const float* op = dir ? bop : fop;
        for (int i = tid; i < 2048; i += 256) ((float4*)s_op)[i] = ((const float4*)op)[i];
    }
    __syncthreads();

    const ScanW p = dir ? bw : fw;
    {
        int d = tid >> 1, nh = tid & 1;
        float dtw0 = p.dtw[0*DIN+d], dtw1 = p.dtw[1*DIN+d];
        float dtw2 = p.dtw[2*DIN+d], dtw3 = p.dtw[3*DIN+d];
        float dtbv = p.dtb[d];
        float Dv   = p.D[d];
        float negA[8];
#pragma unroll
        for (int n = 0; n < 8; n++) negA[n] = -expf(p.Alog[d*DS + nh*8 + n]);
        float hs[8];
#pragma unroll
        for (int n = 0; n < 8; n++) hs[n] = 0.f;

        for (int t = 0; t < SEQ; t++) {
            const float* xr = s_xd + t*XD;
            float dtraw = fmaf(xr[0],dtw0, fmaf(xr[1],dtw1,
                          fmaf(xr[2],dtw2, fmaf(xr[3],dtw3, dtbv))));
            float dt = (dtraw > 20.f) ? dtraw : __logf(1.f + __expf(dtraw));
            float ut = s_u[t*DIN + d];
            float dtu = dt * ut;
            float part = 0.f;
#pragma unroll
            for (int n = 0; n < 8; n++) {
                float a = __expf(dt * negA[n]);
                hs[n] = fmaf(hs[n], a, dtu * xr[4 + nh*8 + n]);
                part  = fmaf(hs[n], xr[20 + nh*8 + n], part);
            }
            part += __shfl_xor_sync(0xffffffffu, part, 1);
            if (nh == 0) s_u[t*DIN + d] = fmaf(ut, Dv, part);
        }
    }
    __syncthreads();

    // gate with silu(z) (z stored in original order)
    {
        const float* zsrc = g_z + rowbase*128;
        for (int i = tid; i < SEQ*DIN; i += 256) {
            int t = i >> 7, d = i & 127;
            int to = dir ? (SEQ-1-t) : t;
            float z = zsrc[to*128 + d];
            s_u[t*DIN + d] *= z / (1.f + __expf(-z));
        }
    }
    __syncthreads();

    // outproj: s = y @ op[128][64]  -> g_s{dir} at original rows
    {
        float* sout = (dir ? g_s1 : g_s0) + (size_t)b*SEQ*64;
        const ull* w8 = (const ull*)s_op;
        int colg = tid & 15, rowg = tid >> 4;
        for (int t0 = rowg; t0 < SEQ; t0 += 64) {
            ull acc[4][2];
#pragma unroll
            for (int ri = 0; ri < 4; ri++) { acc[ri][0] = 0ull; acc[ri][1] = 0ull; }
            int nr = (SEQ - t0 + 15) / 16; if (nr > 4) nr = 4;
#pragma unroll 2
            for (int k = 0; k < 128; k++) {
                ull w0 = w8[k*32 + colg*2], w1 = w8[k*32 + colg*2 + 1];
#pragma unroll
                for (int ri = 0; ri < 4; ri++) {
                    int ts = t0 + ri*16;
                    if (ri < nr) {
                        ull a2 = f2bc(s_u[ts*DIN + k]);
                        acc[ri][0] = f2fma(a2, w0, acc[ri][0]);
                        acc[ri][1] = f2fma(a2, w1, acc[ri][1]);
                    }
                }
            }
#pragma unroll
            for (int ri = 0; ri < 4; ri++) {
                int ts = t0 + ri*16;
                if (ri < nr) {
                    int to = dir ? (SEQ-1-ts) : ts;
                    ull* dst = (ull*)(sout + (size_t)to*64 + colg*4);
                    dst[0] = acc[ri][0]; dst[1] = acc[ri][1];
                }
            }
        }
    }
}

// =================================================================
// K7: LN64(s0+s1)@ov_w+ov_b + x  ->  LN128 @ o_w + o_b  (64 rows/CTA)
// =================================================================
#define K7_TP 132
#define K7_SMEM ((64*128 + 128*128 + 64*65 + 2*64*K7_TP)*4)  // 182528 B
__global__ void __launch_bounds__(256) k7_post(
    const float* __restrict__ ovlnw, const float* __restrict__ ovlnb,
    const float* __restrict__ ovw,   const float* __restrict__ ovb,
    const float* __restrict__ olnw,  const float* __restrict__ olnb,
    const float* __restrict__ ow,    const float* __restrict__ ob,
    const float* __restrict__ xin,   float* __restrict__ out)
{
    extern __shared__ float sm[];
    float* s_vw = sm;                       // [64][128]
    float* s_ow = sm + 8192;                // [128][128]
    float* s_v  = sm + 24576;               // [64][65]
    float* s_t  = sm + 24576 + 64*65;       // [64][132]
    float* s_l  = s_t + 64*K7_TP;           // [64][132]
    int tid = threadIdx.x;
    int base = blockIdx.x * 64;
    int warp = tid >> 5, lane = tid & 31;

    for (int i = tid; i < 2048; i += 256) ((float4*)s_vw)[i] = ((const float4*)ovw)[i];
    for (int i = tid; i < 4096; i += 256) ((float4*)s_ow)[i] = ((const float4*)ow)[i];

#pragma unroll
    for (int j = 0; j < 8; j++) {
        int rl = warp*8 + j;
        size_t row = (size_t)(base + rl);
        float v0 = g_s0[row*64 + lane]      + g_s1[row*64 + lane];
        float v1 = g_s0[row*64 + 32 + lane] + g_s1[row*64 + 32 + lane];
        float sum = v0 + v1, sq = v0*v0 + v1*v1;
#pragma unroll
        for (int off = 16; off; off >>= 1) {
            sum += __shfl_xor_sync(0xffffffffu, sum, off);
            sq  += __shfl_xor_sync(0xffffffffu, sq,  off);
        }
        float mean = sum * (1.f/64.f);
        float var  = sq  * (1.f/64.f) - mean*mean;
        float rstd = rsqrtf(var + 1e-5f);
        s_v[rl*65 + lane]      = (v0-mean)*rstd*ovlnw[lane]    + ovlnb[lane];
        s_v[rl*65 + 32 + lane] = (v1-mean)*rstd*ovlnw[32+lane] + ovlnb[32+lane];
    }
    __syncthreads();

    int colg = tid & 31, rowg = tid >> 5;

    {
        ull b0 = ((const ull*)ovb)[colg*2], b1 = ((const ull*)ovb)[colg*2+1];
        ull acc[8][2];
#pragma unroll
        for (int ri = 0; ri < 8; ri++) { acc[ri][0] = b0; acc[ri][1] = b1; }
        const ull* w8 = (const ull*)s_vw;
#pragma unroll 2
        for (int k = 0; k < 64; k++) {
            ull w0 = w8[k*64 + colg*2], w1 = w8[k*64 + colg*2 + 1];
#pragma unroll
            for (int ri = 0; ri < 8; ri++) {
                ull a2 = f2bc(s_v[(rowg*8+ri)*65 + k]);
                acc[ri][0] = f2fma(a2, w0, acc[ri][0]);
                acc[ri][1] = f2fma(a2, w1, acc[ri][1]);
            }
        }
#pragma unroll
        for (int ri = 0; ri < 8; ri++) {
            int rl = rowg*8 + ri;
            float4 xv = ((const float4*)(xin + (size_t)(base + rl)*128))[colg];
            float2 a0 = f2up(acc[ri][0]), a1 = f2up(acc[ri][1]);
            float4 o;
            o.x = a0.x + xv.x; o.y = a0.y + xv.y;
            o.z = a1.x + xv.z; o.w = a1.y + xv.w;
            ((float4*)(s_t + rl*K7_TP))[colg] = o;
        }
    }
    __syncthreads();

#pragma unroll
    for (int j = 0; j < 8; j++) {
        int rl = warp*8 + j;
        float v[4]; float sum = 0.f, sq = 0.f;
#pragma unroll
        for (int k = 0; k < 4; k++) {
            v[k] = s_t[rl*K7_TP + lane + 32*k];
            sum += v[k]; sq += v[k]*v[k];
        }
#pragma unroll
        for (int off = 16; off; off >>= 1) {
            sum += __shfl_xor_sync(0xffffffffu, sum, off);
            sq  += __shfl_xor_sync(0xffffffffu, sq,  off);
        }
        float mean = sum * (1.f/128.f);
        float var  = sq  * (1.f/128.f) - mean*mean;
        float rstd = rsqrtf(var + 1e-5f);
#pragma unroll
        for (int k = 0; k < 4; k++) {
            int i = lane + 32*k;
            s_l[rl*K7_TP + i] = (v[k]-mean)*rstd*olnw[i] + olnb[i];
        }
    }
    __syncthreads();

    {
        ull b0 = ((const ull*)ob)[colg*2], b1 = ((const ull*)ob)[colg*2+1];
        ull acc[8][2];
#pragma unroll
        for (int ri = 0; ri < 8; ri++) { acc[ri][0] = b0; acc[ri][1] = b1; }
        const ull* w8 = (const ull*)s_ow;
#pragma unroll 2
        for (int k = 0; k < 128; k++) {
            ull w0 = w8[k*64 + colg*2], w1 = w8[k*64 + colg*2 + 1];
#pragma unroll
            for (int ri = 0; ri < 8; ri++) {
                ull a2 = f2bc(s_l[(rowg*8+ri)*K7_TP + k]);
                acc[ri][0] = f2fma(a2, w0, acc[ri][0]);
                acc[ri][1] = f2fma(a2, w1, acc[ri][1]);
            }
        }
#pragma unroll
        for (int ri = 0; ri < 8; ri++) {
            ull* dst = (ull*)(out + (size_t)(base + rowg*8 + ri)*128 + colg*4);
            dst[0] = acc[ri][0]; dst[1] = acc[ri][1];
        }
    }
}

// =================================================================
extern "C" void kernel_launch(void* const* d_in, const int* in_sizes, int n_in,
                              void* d_out, int out_size)
{
    (void)n_in; (void)out_size;

    // dict order -> slot 6 = ov_ln_w (64); signature order -> fw_inproj (16384).
    bool sig_order = (in_sizes[6] > 1024);
    int i_ov, i_fw, i_bw;
    if (sig_order) { i_fw = 6;  i_bw = 15; i_ov = 24; }
    else           { i_ov = 6;  i_fw = 14; i_bw = 23; }

    const float* x     = (const float*)d_in[0];
    const float* qk    = (const float*)d_in[1];
    const float* inlnw = (const float*)d_in[2];
    const float* inlnb = (const float*)d_in[3];
    const float* inw   = (const float*)d_in[4];
    const float* inb   = (const float*)d_in[5];

    const float* fw_ip = (const float*)d_in[i_fw+0];
    const float* fw_cw = (const float*)d_in[i_fw+1];
    const float* fw_cb = (const float*)d_in[i_fw+2];
    const float* fw_xp = (const float*)d_in[i_fw+3];
    ScanW fw { (const float*)d_in[i_fw+4], (const float*)d_in[i_fw+5],
               (const float*)d_in[i_fw+6], (const float*)d_in[i_fw+7] };
    const float* fw_op = (const float*)d_in[i_fw+8];

    const float* bw_ip = (const float*)d_in[i_bw+0];
    const float* bw_cw = (const float*)d_in[i_bw+1];
    const float* bw_cb = (const float*)d_in[i_bw+2];
    const float* bw_xp = (const float*)d_in[i_bw+3];
    ScanW bw { (const float*)d_in[i_bw+4], (const float*)d_in[i_bw+5],
               (const float*)d_in[i_bw+6], (const float*)d_in[i_bw+7] };
    const float* bw_op = (const float*)d_in[i_bw+8];

    const float* ovlnw = (const float*)d_in[i_ov+0];
    const float* ovlnb = (const float*)d_in[i_ov+1];
    const float* ovw   = (const float*)d_in[i_ov+2];
    const float* ovb   = (const float*)d_in[i_ov+3];
    const float* olnw  = (const float*)d_in[i_ov+4];
    const float* olnb  = (const float*)d_in[i_ov+5];
    const float* ow    = (const float*)d_in[i_ov+6];
    const float* ob    = (const float*)d_in[i_ov+7];

    cudaFuncSetAttribute(k1_pre,   cudaFuncAttributeMaxDynamicSharedMemorySize, K1_SMEM);
    cudaFuncSetAttribute(kB_fused, cudaFuncAttributeMaxDynamicSharedMemorySize, KB_SMEM);
    cudaFuncSetAttribute(k5_scan,  cudaFuncAttributeMaxDynamicSharedMemorySize, K5_SMEM);
    cudaFuncSetAttribute(k7_post,  cudaFuncAttributeMaxDynamicSharedMemorySize, K7_SMEM);

    k1_pre  <<<NROWS/64, 256, K1_SMEM>>>(x, qk, inlnw, inlnb, inw, inb);
    kB_fused<<<dim3(3, BT, 2), 256, KB_SMEM>>>(fw_ip, bw_ip, fw_cw, fw_cb,
                                               bw_cw, bw_cb, fw_xp, bw_xp);
    k5_scan <<<dim3(BT, 2), 256, K5_SMEM>>>(fw, bw, fw_op, bw_op);
    k7_post <<<NROWS/64, 256, K7_SMEM>>>(ovlnw, ovlnb, ovw, ovb,
                                         olnw, olnb, ow, ob,
                                         x, (float*)d_out);
}

// round 15
// speedup vs baseline: 1.3398x; 1.2620x over previous
#include <cuda_runtime.h>
#include <cstdint>

typedef unsigned long long ull;

#define BT   192
#define SEQ  207
#define CC   128
#define RED  64
#define DIN  128
#define DS   16
#define XD   36
#define NROWS (BT*SEQ)     // 39744
#define SEG  69            // 3 segments of 69 = 207

// ---------------- scratch (no allocation allowed) ----------------
__device__ float g_h0[NROWS*RED];
__device__ float g_uc[2*NROWS*DIN];
__device__ float g_z [2*NROWS*DIN];
__device__ float g_xd[2*NROWS*XD];
__device__ float g_s0[NROWS*RED];
__device__ float g_s1[NROWS*RED];

// ---------------- f32x2 packed-FMA helpers ----------------
__device__ __forceinline__ ull f2pk(float lo, float hi){ ull r; asm("mov.b64 %0,{%1,%2};" : "=l"(r) : "f"(lo), "f"(hi)); return r; }
__device__ __forceinline__ ull f2bc(float v){ return f2pk(v, v); }
__device__ __forceinline__ ull f2fma(ull a, ull b, ull c){ ull d; asm("fma.rn.f32x2 %0,%1,%2,%3;" : "=l"(d) : "l"(a), "l"(b), "l"(c)); return d; }
__device__ __forceinline__ float2 f2up(ull v){ float2 r; asm("mov.b64 {%0,%1},%2;" : "=f"(r.x), "=f"(r.y) : "l"(v)); return r; }

struct ScanW { const float *dtw, *dtb, *Alog, *D; };

// =================================================================
// K1: h0 = LN_256(concat(x,qk)) @ in_w + in_b    96 rows/CTA, 512 thr
// =================================================================
#define K1_ROWS 96
#define K1_SMEM ((256*64 + K1_ROWS*257)*4)   // 164224 B
__global__ void __launch_bounds__(512) k1_pre(
    const float* __restrict__ x, const float* __restrict__ qk,
    const float* __restrict__ lnw, const float* __restrict__ lnb,
    const float* __restrict__ W,   const float* __restrict__ Wb)
{
    extern __shared__ float sm[];
    float* s_w = sm;              // [256][64]
    float* s_a = sm + 256*64;     // [96][257]
    int tid = threadIdx.x;

    for (int i = tid; i < 4096; i += 512) ((float4*)s_w)[i] = ((const float4*)W)[i];

    int base = blockIdx.x * K1_ROWS;
    int warp = tid >> 5, lane = tid & 31;
#pragma unroll
    for (int j = 0; j < 6; j++) {
        int rl = warp*6 + j;
        size_t row = (size_t)(base + rl);
        const float* xr = x  + row*CC;
        const float* qr = qk + row*CC;
        float v[8], sum = 0.f, sq = 0.f;
#pragma unroll
        for (int k = 0; k < 8; k++) {
            int i = lane + 32*k;
            float val = (i < CC) ? xr[i] : qr[i - CC];
            v[k] = val; sum += val; sq += val*val;
        }
#pragma unroll
        for (int off = 16; off; off >>= 1) {
            sum += __shfl_xor_sync(0xffffffffu, sum, off);
            sq  += __shfl_xor_sync(0xffffffffu, sq,  off);
        }
        float mean = sum * (1.f/256.f);
        float var  = sq  * (1.f/256.f) - mean*mean;
        float rstd = rsqrtf(var + 1e-5f);
#pragma unroll
        for (int k = 0; k < 8; k++) {
            int i = lane + 32*k;
            s_a[rl*257 + i] = (v[k]-mean)*rstd*lnw[i] + lnb[i];
        }
    }
    __syncthreads();

    // GEMM 256->64: thread = 3 rows x 4 cols
    int colg = tid & 15, rowg = tid >> 4;   // rowg 0..31
    ull b0 = ((const ull*)Wb)[colg*2], b1 = ((const ull*)Wb)[colg*2+1];
    ull acc[3][2];
#pragma unroll
    for (int ri = 0; ri < 3; ri++) { acc[ri][0] = b0; acc[ri][1] = b1; }
    const ull* w8 = (const ull*)s_w;
#pragma unroll 2
    for (int k = 0; k < 256; k++) {
        ull w0 = w8[k*32 + colg*2], w1 = w8[k*32 + colg*2 + 1];
#pragma unroll
        for (int ri = 0; ri < 3; ri++) {
            ull a2 = f2bc(s_a[(rowg*3+ri)*257 + k]);
            acc[ri][0] = f2fma(a2, w0, acc[ri][0]);
            acc[ri][1] = f2fma(a2, w1, acc[ri][1]);
        }
    }
#pragma unroll
    for (int ri = 0; ri < 3; ri++) {
        ull* dst = (ull*)(g_h0 + (size_t)(base + rowg*3 + ri)*64 + colg*4);
        dst[0] = acc[ri][0]; dst[1] = acc[ri][1];
    }
}

// =================================================================
// KB: fused inproj + causal conv + silu + xproj + z.   512 thr.
//     CTA = (seg, b, dir).  72 SMEM rows = 3 halo + 69 live.
// =================================================================
#define KB_UP   132
#define KB_H0o  0
#define KB_Uo   (72*64)
#define KB_Wo   (KB_Uo + 72*KB_UP)
#define KB_XPo  (KB_Wo + 64*256)
#define KB_TOT  (KB_XPo + 128*XD)
#define KB_SMEM (KB_TOT*4)             // 140416 B

__global__ void __launch_bounds__(512) kB_fused(
    const float* __restrict__ fip, const float* __restrict__ bip,
    const float* __restrict__ fcw, const float* __restrict__ fcb,
    const float* __restrict__ bcw, const float* __restrict__ bcb,
    const float* __restrict__ fxp, const float* __restrict__ bxp)
{
    extern __shared__ float sm[];
    float* s_h0 = sm + KB_H0o;   // [72][64]
    float* s_u  = sm + KB_Uo;    // [72][132]
    float* s_w  = sm + KB_Wo;    // [64][256]
    float* s_xp = sm + KB_XPo;   // [128][36]

    int seg = blockIdx.x;
    int b   = blockIdx.y;
    int dir = blockIdx.z;
    int s0  = seg * SEG;
    int tid = threadIdx.x;

    const float* ip = dir ? bip : fip;
    const float* xp = dir ? bxp : fxp;

    for (int i = tid; i < 4096; i += 512) ((float4*)s_w)[i]  = ((const float4*)ip)[i];
    for (int i = tid; i < 1152; i += 512) ((float4*)s_xp)[i] = ((const float4*)xp)[i];

    for (int i = tid; i < 72*16; i += 512) {
        int li = i >> 4, c = i & 15;
        int ts = s0 + li - 3;
        float4 v = {0.f,0.f,0.f,0.f};
        if (ts >= 0) {
            int to = dir ? (206 - ts) : ts;
            v = ((const float4*)(g_h0 + ((size_t)b*SEQ + to)*64))[c];
        }
        ((float4*)(s_h0 + li*64))[c] = v;
    }
    __syncthreads();

    // ---- GEMM: [72][64] @ W[64][256]; cols<128 -> s_u, cols>=128 -> g_z ----
    {
        int colg = tid & 63;     // 4 float cols
        int rowg = tid >> 6;     // 8 groups x 9 rows (3 chunks of 3)
        const ull* w8 = (const ull*)s_w;
#pragma unroll
        for (int chunk = 0; chunk < 3; chunk++) {
            int r0 = rowg*9 + chunk*3;
            ull acc[3][2];
#pragma unroll
            for (int ri = 0; ri < 3; ri++) { acc[ri][0] = 0ull; acc[ri][1] = 0ull; }
#pragma unroll 2
            for (int k = 0; k < 64; k++) {
                ull w0 = w8[k*128 + colg*2], w1 = w8[k*128 + colg*2 + 1];
#pragma unroll
                for (int ri = 0; ri < 3; ri++) {
                    ull a2 = f2bc(s_h0[(r0+ri)*64 + k]);
                    acc[ri][0] = f2fma(a2, w0, acc[ri][0]);
                    acc[ri][1] = f2fma(a2, w1, acc[ri][1]);
                }
            }
            if (colg < 32) {
#pragma unroll
                for (int ri = 0; ri < 3; ri++) {
                    ull* dst = (ull*)(s_u + (r0+ri)*KB_UP + colg*4);
                    dst[0] = acc[ri][0]; dst[1] = acc[ri][1];
                }
            } else {
                int zc = colg*4 - 128;
#pragma unroll
                for (int ri = 0; ri < 3; ri++) {
                    int li = r0 + ri;
                    if (li >= 3) {
                        int ts = s0 + li - 3;
                        int to = dir ? (206 - ts) : ts;
                        ull* dst = (ull*)(g_z + ((size_t)dir*NROWS + (size_t)b*SEQ + to)*128 + zc);
                        dst[0] = acc[ri][0]; dst[1] = acc[ri][1];
                    }
                }
            }
        }
    }
    __syncthreads();

    // ---- conv(K=4) + silu in place over s_u rows [3,72), 4 quarters ----
    {
        int d = tid & 127, q = tid >> 7;
        const int l0s[4] = {3, 21, 38, 55};
        const int l1s[4] = {21, 38, 55, 72};
        const float* cw = dir ? bcw : fcw;
        const float* cb = dir ? bcb : fcb;
        float w0 = cw[d*4+0], w1 = cw[d*4+1], w2 = cw[d*4+2], w3 = cw[d*4+3];
        float bb = cb[d];
        int l0 = l0s[q], l1 = l1s[q];
        float p3 = s_u[(l0-3)*KB_UP + d];
        float p2 = s_u[(l0-2)*KB_UP + d];
        float p1 = s_u[(l0-1)*KB_UP + d];
        __syncthreads();                 // halo pre-reads before in-place writes
        float* ucg = g_uc + ((size_t)dir*NROWS + (size_t)b*SEQ)*128 + d;
        for (int li = l0; li < l1; li++) {
            float cur = s_u[li*KB_UP + d];
            float v = fmaf(w0,p3, fmaf(w1,p2, fmaf(w2,p1, fmaf(w3,cur, bb))));
            v = v / (1.f + __expf(-v));
            s_u[li*KB_UP + d] = v;
            ucg[(s0 + li - 3)*128] = v;
            p3 = p2; p2 = p1; p1 = cur;
        }
    }
    __syncthreads();

    // ---- xproj: uc rows [3,72) @ xp[128][36] -> g_xd ----
    if (tid < 6*SEG) {                      // 414 threads
        int r = tid / 6, j = tid % 6;       // j: 3 ull cols
        int li = r + 3;
        int ts = s0 + r;
        const ull* w8 = (const ull*)s_xp;   // [128][18] ull
        const float* ur = s_u + li*KB_UP;
        ull acc[3];
#pragma unroll
        for (int c = 0; c < 3; c++) acc[c] = 0ull;
#pragma unroll 4
        for (int k = 0; k < 128; k++) {
            ull a2 = f2bc(ur[k]);
#pragma unroll
            for (int c = 0; c < 3; c++)
                acc[c] = f2fma(a2, w8[k*18 + j*3 + c], acc[c]);
        }
        ull* dst = (ull*)(g_xd + ((size_t)dir*NROWS + (size_t)b*SEQ + ts)*XD + j*6);
#pragma unroll
        for (int c = 0; c < 3; c++) dst[c] = acc[c];
    }
}

// =================================================================
// K5: scan + gate + outproj.  CTA per (b,dir); 512 thr, 4/channel.
// =================================================================
#define K5_SMEM ((SEQ*DIN + SEQ*XD + 128*64)*4)   // 168560 B
__global__ void __launch_bounds__(512, 1) k5_scan(
    ScanW fw, ScanW bw,
    const float* __restrict__ fop, const float* __restrict__ bop)
{
    extern __shared__ float sm[];
    float* s_u  = sm;                      // [207][128]
    float* s_xd = sm + SEQ*DIN;            // [207][36]
    float* s_op = sm + SEQ*DIN + SEQ*XD;   // [128][64]
    int b = blockIdx.x, dir = blockIdx.y;
    int tid = threadIdx.x;
    size_t rowbase = (size_t)dir*NROWS + (size_t)b*SEQ;

    for (int i = tid; i < SEQ*DIN/4; i += 512)
        ((float4*)s_u)[i] = ((const float4*)(g_uc + rowbase*128))[i];
    for (int i = tid; i < SEQ*XD/4; i += 512)
        ((float4*)s_xd)[i] = ((const float4*)(g_xd + rowbase*XD))[i];
    {
        const float* op = dir ? bop : fop;
        for (int i = tid; i < 2048; i += 512) ((float4*)s_op)[i] = ((const float4*)op)[i];
    }
    __syncthreads();

    const ScanW p = dir ? bw : fw;
    {
        int d = tid >> 2, nh = tid & 3;     // 4 states per thread
        float dtw0 = p.dtw[0*DIN+d], dtw1 = p.dtw[1*DIN+d];
        float dtw2 = p.dtw[2*DIN+d], dtw3 = p.dtw[3*DIN+d];
        float dtbv = p.dtb[d];
        float Dv   = p.D[d];
        float negA[4];
#pragma unroll
        for (int n = 0; n < 4; n++) negA[n] = -expf(p.Alog[d*DS + nh*4 + n]);
        float hs[4];
#pragma unroll
        for (int n = 0; n < 4; n++) hs[n] = 0.f;

        for (int t = 0; t < SEQ; t++) {
            const float* xr = s_xd + t*XD;
            float dtraw = fmaf(xr[0],dtw0, fmaf(xr[1],dtw1,
                          fmaf(xr[2],dtw2, fmaf(xr[3],dtw3, dtbv))));
            float dt = (dtraw > 20.f) ? dtraw : __logf(1.f + __expf(dtraw));
            float ut = s_u[t*DIN + d];
            float dtu = dt * ut;
            float part = 0.f;
#pragma unroll
            for (int n = 0; n < 4; n++) {
                float a = __expf(dt * negA[n]);
                hs[n] = fmaf(hs[n], a, dtu * xr[4 + nh*4 + n]);
                part  = fmaf(hs[n], xr[20 + nh*4 + n], part);
            }
            part += __shfl_xor_sync(0xffffffffu, part, 1);
            part += __shfl_xor_sync(0xffffffffu, part, 2);
            if (nh == 0) s_u[t*DIN + d] = fmaf(ut, Dv, part);
        }
    }
    __syncthreads();

    // gate with silu(z) (z stored in original order)
    {
        const float* zsrc = g_z + rowbase*128;
        for (int i = tid; i < SEQ*DIN; i += 512) {
            int t = i >> 7, d = i & 127;
            int to = dir ? (SEQ-1-t) : t;
            float z = zsrc[to*128 + d];
            s_u[t*DIN + d] *= z / (1.f + __expf(-z));
        }
    }
    __syncthreads();

    // outproj: s = y @ op[128][64] -> g_s{dir} at original rows
    {
        float* sout = (dir ? g_s1 : g_s0) + (size_t)b*SEQ*64;
        const ull* w8 = (const ull*)s_op;
        int colg = tid & 15, rowg = tid >> 4;    // 32 row groups
        for (int t = rowg; t < SEQ; t += 32) {
            ull acc0 = 0ull, acc1 = 0ull;
            const float* yr = s_u + t*DIN;
#pragma unroll 4
            for (int k = 0; k < 128; k++) {
                ull a2 = f2bc(yr[k]);
                acc0 = f2fma(a2, w8[k*32 + colg*2],     acc0);
                acc1 = f2fma(a2, w8[k*32 + colg*2 + 1], acc1);
            }
            int to = dir ? (SEQ-1-t) : t;
            ull* dst = (ull*)(sout + (size_t)to*64 + colg*4);
            dst[0] = acc0; dst[1] = acc1;
        }
    }
}

// =================================================================
// K7: LN64(s0+s1)@ov_w+ov_b + x -> LN128 @ o_w + o_b.  96 rows, 512 thr
// =================================================================
#define K7_ROWS 96
#define K7_TP 132
#define K7_SMEM ((64*128 + 128*128 + K7_ROWS*65 + K7_ROWS*K7_TP)*4)  // 174208 B
__global__ void __launch_bounds__(512) k7_post(
    const float* __restrict__ ovlnw, const float* __restrict__ ovlnb,
    const float* __restrict__ ovw,   const float* __restrict__ ovb,
    const float* __restrict__ olnw,  const float* __restrict__ olnb,
    const float* __restrict__ ow,    const float* __restrict__ ob,
    const float* __restrict__ xin,   float* __restrict__ out)
{
    extern __shared__ float sm[];
    float* s_vw = sm;                        // [64][128]
    float* s_ow = sm + 8192;                 // [128][128]
    float* s_v  = sm + 24576;                // [96][65]
    float* s_t  = s_v + K7_ROWS*65;          // [96][132]  (LN128 done in place)
    int tid = threadIdx.x;
    int base = blockIdx.x * K7_ROWS;
    int warp = tid >> 5, lane = tid & 31;

    for (int i = tid; i < 2048; i += 512) ((float4*)s_vw)[i] = ((const float4*)ovw)[i];
    for (int i = tid; i < 4096; i += 512) ((float4*)s_ow)[i] = ((const float4*)ow)[i];

    // LN64 of (s0+s1): warp handles 6 rows
#pragma unroll
    for (int j = 0; j < 6; j++) {
        int rl = warp*6 + j;
        size_t row = (size_t)(base + rl);
        float v0 = g_s0[row*64 + lane]      + g_s1[row*64 + lane];
        float v1 = g_s0[row*64 + 32 + lane] + g_s1[row*64 + 32 + lane];
        float sum = v0 + v1, sq = v0*v0 + v1*v1;
#pragma unroll
        for (int off = 16; off; off >>= 1) {
            sum += __shfl_xor_sync(0xffffffffu, sum, off);
            sq  += __shfl_xor_sync(0xffffffffu, sq,  off);
        }
        float mean = sum * (1.f/64.f);
        float var  = sq  * (1.f/64.f) - mean*mean;
        float rstd = rsqrtf(var + 1e-5f);
        s_v[rl*65 + lane]      = (v0-mean)*rstd*ovlnw[lane]    + ovlnb[lane];
        s_v[rl*65 + 32 + lane] = (v1-mean)*rstd*ovlnw[32+lane] + ovlnb[32+lane];
    }
    __syncthreads();

    int colg = tid & 31, rowg = tid >> 5;   // 16 row groups x 6 rows

    // GEMM1 64->128 + bias + residual -> s_t
    {
        ull b0 = ((const ull*)ovb)[colg*2], b1 = ((const ull*)ovb)[colg*2+1];
        ull acc[6][2];
#pragma unroll
        for (int ri = 0; ri < 6; ri++) { acc[ri][0] = b0; acc[ri][1] = b1; }
        const ull* w8 = (const ull*)s_vw;
#pragma unroll 2
        for (int k = 0; k < 64; k++) {
            ull w0 = w8[k*64 + colg*2], w1 = w8[k*64 + colg*2 + 1];
#pragma unroll
            for (int ri = 0; ri < 6; ri++) {
                ull a2 = f2bc(s_v[(rowg*6+ri)*65 + k]);
                acc[ri][0] = f2fma(a2, w0, acc[ri][0]);
                acc[ri][1] = f2fma(a2, w1, acc[ri][1]);
            }
        }
#pragma unroll
        for (int ri = 0; ri < 6; ri++) {
            int rl = rowg*6 + ri;
            float4 xv = ((const float4*)(xin + (size_t)(base + rl)*128))[colg];
            float2 a0 = f2up(acc[ri][0]), a1 = f2up(acc[ri][1]);
            float4 o;
            o.x = a0.x + xv.x; o.y = a0.y + xv.y;
            o.z = a1.x + xv.z; o.w = a1.y + xv.w;
            ((float4*)(s_t + rl*K7_TP))[colg] = o;
        }
    }
    __syncthreads();

    // LN128 IN PLACE in s_t (each row owned by one warp; values in regs)
#pragma unroll
    for (int j = 0; j < 6; j++) {
        int rl = warp*6 + j;
        float v[4]; float sum = 0.f, sq = 0.f;
#pragma unroll
        for (int k = 0; k < 4; k++) {
            v[k] = s_t[rl*K7_TP + lane + 32*k];
            sum += v[k]; sq += v[k]*v[k];
        }
#pragma unroll
        for (int off = 16; off; off >>= 1) {
            sum += __shfl_xor_sync(0xffffffffu, sum, off);
            sq  += __shfl_xor_sync(0xffffffffu, sq,  off);
        }
        float mean = sum * (1.f/128.f);
        float var  = sq  * (1.f/128.f) - mean*mean;
        float rstd = rsqrtf(var + 1e-5f);
#pragma unroll
        for (int k = 0; k < 4; k++) {
            int i = lane + 32*k;
            s_t[rl*K7_TP + i] = (v[k]-mean)*rstd*olnw[i] + olnb[i];
        }
    }
    __syncthreads();

    // GEMM2 128->128
    {
        ull b0 = ((const ull*)ob)[colg*2], b1 = ((const ull*)ob)[colg*2+1];
        ull acc[6][2];
#pragma unroll
        for (int ri = 0; ri < 6; ri++) { acc[ri][0] = b0; acc[ri][1] = b1; }
        const ull* w8 = (const ull*)s_ow;
#pragma unroll 2
        for (int k = 0; k < 128; k++) {
            ull w0 = w8[k*64 + colg*2], w1 = w8[k*64 + colg*2 + 1];
#pragma unroll
            for (int ri = 0; ri < 6; ri++) {
                ull a2 = f2bc(s_t[(rowg*6+ri)*K7_TP + k]);
                acc[ri][0] = f2fma(a2, w0, acc[ri][0]);
                acc[ri][1] = f2fma(a2, w1, acc[ri][1]);
            }
        }
#pragma unroll
        for (int ri = 0; ri < 6; ri++) {
            ull* dst = (ull*)(out + (size_t)(base + rowg*6 + ri)*128 + colg*4);
            dst[0] = acc[ri][0]; dst[1] = acc[ri][1];
        }
    }
}

// =================================================================
extern "C" void kernel_launch(void* const* d_in, const int* in_sizes, int n_in,
                              void* d_out, int out_size)
{
    (void)n_in; (void)out_size;

    bool sig_order = (in_sizes[6] > 1024);
    int i_ov, i_fw, i_bw;
    if (sig_order) { i_fw = 6;  i_bw = 15; i_ov = 24; }
    else           { i_ov = 6;  i_fw = 14; i_bw = 23; }

    const float* x     = (const float*)d_in[0];
    const float* qk    = (const float*)d_in[1];
    const float* inlnw = (const float*)d_in[2];
    const float* inlnb = (const float*)d_in[3];
    const float* inw   = (const float*)d_in[4];
    const float* inb   = (const float*)d_in[5];

    const float* fw_ip = (const float*)d_in[i_fw+0];
    const float* fw_cw = (const float*)d_in[i_fw+1];
    const float* fw_cb = (const float*)d_in[i_fw+2];
    const float* fw_xp = (const float*)d_in[i_fw+3];
    ScanW fw { (const float*)d_in[i_fw+4], (const float*)d_in[i_fw+5],
               (const float*)d_in[i_fw+6], (const float*)d_in[i_fw+7] };
    const float* fw_op = (const float*)d_in[i_fw+8];

    const float* bw_ip = (const float*)d_in[i_bw+0];
    const float* bw_cw = (const float*)d_in[i_bw+1];
    const float* bw_cb = (const float*)d_in[i_bw+2];
    const float* bw_xp = (const float*)d_in[i_bw+3];
    ScanW bw { (const float*)d_in[i_bw+4], (const float*)d_in[i_bw+5],
               (const float*)d_in[i_bw+6], (const float*)d_in[i_bw+7] };
    const float* bw_op = (const float*)d_in[i_bw+8];

    const float* ovlnw = (const float*)d_in[i_ov+0];
    const float* ovlnb = (const float*)d_in[i_ov+1];
    const float* ovw   = (const float*)d_in[i_ov+2];
    const float* ovb   = (const float*)d_in[i_ov+3];
    const float* olnw  = (const float*)d_in[i_ov+4];
    const float* olnb  = (const float*)d_in[i_ov+5];
    const float* ow    = (const float*)d_in[i_ov+6];
    const float* ob    = (const float*)d_in[i_ov+7];

    cudaFuncSetAttribute(k1_pre,   cudaFuncAttributeMaxDynamicSharedMemorySize, K1_SMEM);
    cudaFuncSetAttribute(kB_fused, cudaFuncAttributeMaxDynamicSharedMemorySize, KB_SMEM);
    cudaFuncSetAttribute(k5_scan,  cudaFuncAttributeMaxDynamicSharedMemorySize, K5_SMEM);
    cudaFuncSetAttribute(k7_post,  cudaFuncAttributeMaxDynamicSharedMemorySize, K7_SMEM);

    k1_pre  <<<NROWS/K1_ROWS, 512, K1_SMEM>>>(x, qk, inlnw, inlnb, inw, inb);
    kB_fused<<<dim3(3, BT, 2), 512, KB_SMEM>>>(fw_ip, bw_ip, fw_cw, fw_cb,
                                               bw_cw, bw_cb, fw_xp, bw_xp);
    k5_scan <<<dim3(BT, 2), 512, K5_SMEM>>>(fw, bw, fw_op, bw_op);
    k7_post <<<NROWS/K7_ROWS, 512, K7_SMEM>>>(ovlnw, ovlnb, ovw, ovb,
                                              olnw, olnb, ow, ob,
                                              x, (float*)d_out);
}